// round 4
// baseline (speedup 1.0000x reference)
#include <cuda_runtime.h>
#include <math.h>
#include <stdint.h>

#define B 64
#define S 512
#define H 1024
#define E 10
#define G4 4096
#define LSTM_IN 1035

// output packing offsets (flattened pytree order)
#define OFF_FIN 0
#define OFF_H   64
#define OFF_C   (64 + B*H)
#define OFF_A   (64 + 2*B*H)
#define OFF_S   (64 + 2*B*H + B*S)

// attn tiling: block 128(bs) x 256(g), BK=32, 3-stage cp.async pipeline
#define BM 128
#define BN 256
#define BK 32
#define NITER (H / BK)              // 32
#define PADK 36                      // floats per smem row (pad 32->36)
#define A_STAGE (BM * PADK * 4)      // 18432 B
#define B_STAGE (BN * PADK * 4)      // 36864 B
#define STAGE   (A_STAGE + B_STAGE)  // 55296 B
#define NSTAGE 3
#define R_DP (NSTAGE * STAGE)
#define R_WV (R_DP + BN * 4)
#define ATTN_SMEM (R_WV + BN * 4)    // ~168 KB

// scratch (no allocation allowed)
__device__ float g_dec_proj[B*H];
__device__ float g_scores[B*S];
__device__ float g_context[B*H];
__device__ float g_gates[B*G4];
__device__ float g_sim[B*E];

__device__ __forceinline__ float sigmoidf_(float x) { return 1.f / (1.f + expf(-x)); }

__device__ __forceinline__ uint32_t smem_u32(const void* p) {
    uint32_t a;
    asm("{ .reg .u64 t; cvta.to.shared.u64 t, %1; cvt.u32.u64 %0, t; }" : "=r"(a) : "l"(p));
    return a;
}

__device__ __forceinline__ void cp_async16(uint32_t dst, const void* src) {
    asm volatile("cp.async.cg.shared.global [%0], [%1], 16;" :: "r"(dst), "l"(src));
}
#define CP_COMMIT() asm volatile("cp.async.commit_group;" ::: "memory")

// raw fp32 operands: HMMA.TF32 truncates low mantissa bits in hardware
__device__ __forceinline__ void mma_tf32(float c[4], const uint32_t a[4], const uint32_t b[2]) {
    asm volatile(
        "mma.sync.aligned.m16n8k8.row.col.f32.tf32.tf32.f32 "
        "{%0,%1,%2,%3}, {%4,%5,%6,%7}, {%8,%9}, {%0,%1,%2,%3};\n"
        : "+f"(c[0]), "+f"(c[1]), "+f"(c[2]), "+f"(c[3])
        : "r"(a[0]), "r"(a[1]), "r"(a[2]), "r"(a[3]), "r"(b[0]), "r"(b[1]));
}

// ---------------------------------------------------------------------------
__global__ void k_zero() {
    int i = blockIdx.x * blockDim.x + threadIdx.x;
    if (i < B*S) g_scores[i] = 0.f;
}

// ---------------------------------------------------------------------------
// Fused attention-score GEMM via mma.sync tf32 + cp.async 3-stage pipeline.
//   scores[row] += sum_g w_val[g] * tanh(dec_proj[b,g] + enc[row,:] . W_enc[g,:])
// Block tile 128 x 256, 8 warps as 2M x 4N (warp tile 64x64).
// grid = (H/BN = 4 [g fastest for L2 reuse of enc], B*S/BM = 256)
// ---------------------------------------------------------------------------
__global__ void __launch_bounds__(256) k_attn_tc(
    const float* __restrict__ enc,
    const float* __restrict__ Wenc,
    const float* __restrict__ w_val)
{
    extern __shared__ char smem[];
    const uint32_t sb = smem_u32(smem);
    const int tid = threadIdx.x;
    const int lane = tid & 31, warp = tid >> 5;
    const int warpM = warp & 1, warpN = warp >> 1;
    const int group = lane >> 2, tid4 = lane & 3;

    const int gBase   = blockIdx.x * BN;
    const int rowBase = blockIdx.y * BM;
    const int b = rowBase / S;

    float* dp_s = (float*)(smem + R_DP);
    float* wv_s = (float*)(smem + R_WV);
    dp_s[tid] = g_dec_proj[b*H + gBase + tid];
    wv_s[tid] = w_val[gBase + tid];

    const float* Ag = enc  + (size_t)rowBase * H;
    const float* Bg = Wenc + (size_t)gBase   * H;

    auto issue = [&](int it, int stg) {
        uint32_t sa  = sb + stg * STAGE;
        uint32_t sbB = sa + A_STAGE;
        int k0 = it * BK;
#pragma unroll
        for (int i = 0; i < 4; i++) {            // A: 128 rows x 8 chunks
            int c = tid + 256 * i;
            int r = c >> 3, col = c & 7;
            cp_async16(sa + r * (PADK*4) + col * 16, Ag + (size_t)r * H + k0 + col * 4);
        }
#pragma unroll
        for (int i = 0; i < 8; i++) {            // B: 256 rows x 8 chunks
            int c = tid + 256 * i;
            int r = c >> 3, col = c & 7;
            cp_async16(sbB + r * (PADK*4) + col * 16, Bg + (size_t)r * H + k0 + col * 4);
        }
        CP_COMMIT();
    };

    float acc[4][8][4];
#pragma unroll
    for (int mi = 0; mi < 4; mi++)
#pragma unroll
        for (int ni = 0; ni < 8; ni++)
#pragma unroll
            for (int q = 0; q < 4; q++) acc[mi][ni][q] = 0.f;

    issue(0, 0);
    issue(1, 1);

    for (int it = 0; it < NITER; it++) {
        if (it < NITER - 1) { asm volatile("cp.async.wait_group 1;" ::: "memory"); }
        else                { asm volatile("cp.async.wait_group 0;" ::: "memory"); }
        __syncthreads();
        if (it + 2 < NITER) issue(it + 2, (it + 2) % NSTAGE);

        const float* As = (const float*)(smem + (it % NSTAGE) * STAGE);
        const float* Bs = (const float*)(smem + (it % NSTAGE) * STAGE + A_STAGE);

#pragma unroll
        for (int k8 = 0; k8 < 4; k8++) {
            int kk = k8 * 8;
            uint32_t afr[4][4], bfr[8][2];
#pragma unroll
            for (int mi = 0; mi < 4; mi++) {
                int m = warpM*64 + mi*16 + group;
                afr[mi][0] = __float_as_uint(As[(m    )*PADK + kk + tid4    ]);
                afr[mi][1] = __float_as_uint(As[(m + 8)*PADK + kk + tid4    ]);
                afr[mi][2] = __float_as_uint(As[(m    )*PADK + kk + tid4 + 4]);
                afr[mi][3] = __float_as_uint(As[(m + 8)*PADK + kk + tid4 + 4]);
            }
#pragma unroll
            for (int ni = 0; ni < 8; ni++) {
                int n = warpN*64 + ni*8 + group;
                bfr[ni][0] = __float_as_uint(Bs[n*PADK + kk + tid4    ]);
                bfr[ni][1] = __float_as_uint(Bs[n*PADK + kk + tid4 + 4]);
            }
#pragma unroll
            for (int mi = 0; mi < 4; mi++)
#pragma unroll
                for (int ni = 0; ni < 8; ni++)
                    mma_tf32(acc[mi][ni], afr[mi], bfr[ni]);
        }
        __syncthreads();
    }

    // epilogue: tanh + w_val dot over warp's 64 g-cols, quad shfl reduce, atomic
#pragma unroll
    for (int mi = 0; mi < 4; mi++) {
        float p0 = 0.f, p1 = 0.f;
#pragma unroll
        for (int ni = 0; ni < 8; ni++)
#pragma unroll
            for (int q = 0; q < 2; q++) {
                int g = warpN*64 + ni*8 + 2*tid4 + q;
                float wv = wv_s[g], dp = dp_s[g];
                p0 += wv * tanhf(acc[mi][ni][q    ] + dp);
                p1 += wv * tanhf(acc[mi][ni][2 + q] + dp);
            }
        p0 += __shfl_down_sync(0xffffffffu, p0, 2, 4);
        p0 += __shfl_down_sync(0xffffffffu, p0, 1, 4);
        p1 += __shfl_down_sync(0xffffffffu, p1, 2, 4);
        p1 += __shfl_down_sync(0xffffffffu, p1, 1, 4);
        if (tid4 == 0) {
            int row = rowBase + warpM*64 + mi*16 + group;
            atomicAdd(&g_scores[row    ], p0);
            atomicAdd(&g_scores[row + 8], p1);
        }
    }
}

// ---------------------------------------------------------------------------
// Small 64-row GEMM on tensor cores:
//   C[64, N] (+)= A0[64,1024] @ W0[:, :1024]^T  (+ A1[64,1024] @ W1[:, :1024]^T)
// Block 64x128, 8 warps as 2M x 4N (warp tile 32x32). No split-K, no atomics.
// ---------------------------------------------------------------------------
__global__ void __launch_bounds__(256) k_tc64(
    const float* __restrict__ A0, const float* __restrict__ W0, int ldw0,
    const float* __restrict__ A1, const float* __restrict__ W1, int ldw1,
    float* __restrict__ C, int ldc, int addC)
{
    __shared__ float As[64 * PADK];
    __shared__ float Ws[128 * PADK];
    const int tid = threadIdx.x;
    const int lane = tid & 31, warp = tid >> 5;
    const int warpM = warp & 1, warpN = warp >> 1;
    const int group = lane >> 2, tid4 = lane & 3;
    const int nBase = blockIdx.x * 128;

    float acc[2][4][4];
#pragma unroll
    for (int mi = 0; mi < 2; mi++)
#pragma unroll
        for (int ni = 0; ni < 4; ni++)
#pragma unroll
            for (int q = 0; q < 4; q++) acc[mi][ni][q] = 0.f;

    for (int src = 0; src < 2; src++) {
        const float* A = src ? A1 : A0;
        const float* W = src ? W1 : W0;
        int ldw = src ? ldw1 : ldw0;
        if (A == nullptr) break;

        for (int k0 = 0; k0 < H; k0 += BK) {
#pragma unroll
            for (int i = 0; i < 8; i++) {        // A: 64x32 floats
                int e = tid + 256 * i;
                As[(e >> 5) * PADK + (e & 31)] = A[(size_t)(e >> 5) * H + k0 + (e & 31)];
            }
#pragma unroll
            for (int i = 0; i < 16; i++) {       // W: 128x32 floats
                int e = tid + 256 * i;
                Ws[(e >> 5) * PADK + (e & 31)] = W[(size_t)(nBase + (e >> 5)) * ldw + k0 + (e & 31)];
            }
            __syncthreads();
#pragma unroll
            for (int k8 = 0; k8 < 4; k8++) {
                int kk = k8 * 8;
                uint32_t afr[2][4], bfr[4][2];
#pragma unroll
                for (int mi = 0; mi < 2; mi++) {
                    int m = warpM*32 + mi*16 + group;
                    afr[mi][0] = __float_as_uint(As[(m    )*PADK + kk + tid4    ]);
                    afr[mi][1] = __float_as_uint(As[(m + 8)*PADK + kk + tid4    ]);
                    afr[mi][2] = __float_as_uint(As[(m    )*PADK + kk + tid4 + 4]);
                    afr[mi][3] = __float_as_uint(As[(m + 8)*PADK + kk + tid4 + 4]);
                }
#pragma unroll
                for (int ni = 0; ni < 4; ni++) {
                    int n = warpN*32 + ni*8 + group;
                    bfr[ni][0] = __float_as_uint(Ws[n*PADK + kk + tid4    ]);
                    bfr[ni][1] = __float_as_uint(Ws[n*PADK + kk + tid4 + 4]);
                }
#pragma unroll
                for (int mi = 0; mi < 2; mi++)
#pragma unroll
                    for (int ni = 0; ni < 4; ni++)
                        mma_tf32(acc[mi][ni], afr[mi], bfr[ni]);
            }
            __syncthreads();
        }
    }

#pragma unroll
    for (int mi = 0; mi < 2; mi++)
#pragma unroll
        for (int ni = 0; ni < 4; ni++) {
            int row = warpM*32 + mi*16 + group;
            int col = nBase + warpN*32 + ni*8 + 2*tid4;
            float v0 = acc[mi][ni][0], v1 = acc[mi][ni][1];
            float v2 = acc[mi][ni][2], v3 = acc[mi][ni][3];
            if (addC) {
                v0 += C[(size_t)row*ldc + col];       v1 += C[(size_t)row*ldc + col + 1];
                v2 += C[(size_t)(row+8)*ldc + col];   v3 += C[(size_t)(row+8)*ldc + col + 1];
            }
            C[(size_t)row*ldc + col]         = v0;
            C[(size_t)row*ldc + col + 1]     = v1;
            C[(size_t)(row+8)*ldc + col]     = v2;
            C[(size_t)(row+8)*ldc + col + 1] = v3;
        }
}

// ---------------------------------------------------------------------------
__global__ void k_softmax(float* __restrict__ out)
{
    int b = blockIdx.x, tid = threadIdx.x;
    __shared__ float red[256];
    float s0 = g_scores[b*S + tid];
    float s1 = g_scores[b*S + 256 + tid];
    red[tid] = fmaxf(s0, s1);
    __syncthreads();
    for (int off = 128; off > 0; off >>= 1) {
        if (tid < off) red[tid] = fmaxf(red[tid], red[tid + off]);
        __syncthreads();
    }
    float m = red[0];
    __syncthreads();
    float e0 = expf(s0 - m), e1 = expf(s1 - m);
    red[tid] = e0 + e1;
    __syncthreads();
    for (int off = 128; off > 0; off >>= 1) {
        if (tid < off) red[tid] += red[tid + off];
        __syncthreads();
    }
    float inv = 1.f / red[0];
    out[OFF_A + b*S + tid]       = e0 * inv;
    out[OFF_A + b*S + 256 + tid] = e1 * inv;
}

// ---------------------------------------------------------------------------
__global__ void k_context(const float* __restrict__ enc, const float* __restrict__ out)
{
    int b = blockIdx.x;
    int h = blockIdx.y * 256 + threadIdx.x;
    __shared__ float w[S];
    for (int s = threadIdx.x; s < S; s += 256) w[s] = out[OFF_A + b*S + s];
    __syncthreads();
    const float* p = enc + (size_t)b * S * H + h;
    float a0 = 0.f, a1 = 0.f, a2 = 0.f, a3 = 0.f;
#pragma unroll 4
    for (int s = 0; s < S; s += 4) {
        a0 += w[s]     * p[(size_t)s * H];
        a1 += w[s + 1] * p[(size_t)(s + 1) * H];
        a2 += w[s + 2] * p[(size_t)(s + 2) * H];
        a3 += w[s + 3] * p[(size_t)(s + 3) * H];
    }
    g_context[b*H + h] = (a0 + a1) + (a2 + a3);
}

// ---------------------------------------------------------------------------
__global__ void k_sim(const float* __restrict__ events,
                      const float* __restrict__ W_gate,
                      float* __restrict__ out)
{
    int b = blockIdx.x;
    int tid = threadIdx.x, warp = tid >> 5, lane = tid & 31;
    __shared__ float t[E];
    if (warp < E) {
        float acc = 0.f;
        for (int h = lane; h < H; h += 32)
            acc += g_context[b*H + h] * events[warp*H + h];
#pragma unroll
        for (int off = 16; off > 0; off >>= 1)
            acc += __shfl_down_sync(0xffffffffu, acc, off);
        if (lane == 0) t[warp] = acc;
    }
    __syncthreads();
    if (tid < E) {
        float s = 0.f;
#pragma unroll
        for (int e = 0; e < E; e++) s += t[e] * W_gate[tid*E + e];
        g_sim[b*E + tid] = s;
        out[OFF_S + b*E + tid] = s;
    }
}

// ---------------------------------------------------------------------------
__global__ void k_gates_init(const float* __restrict__ x,
                             const float* __restrict__ W_ih,
                             const float* __restrict__ b_ih,
                             const float* __restrict__ b_hh)
{
    int b = blockIdx.x;
    int j = blockIdx.y * 256 + threadIdx.x;
    const float* wr = W_ih + (size_t)j * LSTM_IN;
    float v = b_ih[j] + b_hh[j] + x[b] * wr[1034];
#pragma unroll
    for (int e = 0; e < E; e++) v += g_sim[b*E + e] * wr[1024 + e];
    g_gates[b*G4 + j] = v;
}

// ---------------------------------------------------------------------------
__global__ void k_lstm_final(const float* __restrict__ c0,
                             const float* __restrict__ ln_g,
                             const float* __restrict__ ln_b,
                             const float* __restrict__ W_fin,
                             const float* __restrict__ b_fin,
                             float* __restrict__ out)
{
    int b = blockIdx.x, tid = threadIdx.x;
    __shared__ float red[256];
    float hv[4];
    float sum = 0.f;
#pragma unroll
    for (int r = 0; r < 4; r++) {
        int h = r*256 + tid;
        float ig = g_gates[b*G4 + h];
        float fg = g_gates[b*G4 + 1024 + h];
        float gg = g_gates[b*G4 + 2048 + h];
        float og = g_gates[b*G4 + 3072 + h];
        float cn = sigmoidf_(fg) * c0[b*H + h] + sigmoidf_(ig) * tanhf(gg);
        float hn = sigmoidf_(og) * tanhf(cn);
        out[OFF_H + b*H + h] = hn;
        out[OFF_C + b*H + h] = cn;
        hv[r] = hn;
        sum += hn;
    }
    red[tid] = sum; __syncthreads();
    for (int off = 128; off > 0; off >>= 1) {
        if (tid < off) red[tid] += red[tid + off];
        __syncthreads();
    }
    float mu = red[0] * (1.f / H);
    __syncthreads();
    float sq = 0.f;
#pragma unroll
    for (int r = 0; r < 4; r++) { float d = hv[r] - mu; sq += d * d; }
    red[tid] = sq; __syncthreads();
    for (int off = 128; off > 0; off >>= 1) {
        if (tid < off) red[tid] += red[tid + off];
        __syncthreads();
    }
    float rstd = rsqrtf(red[0] * (1.f / H) + 1e-5f);
    __syncthreads();
    float fp = 0.f;
#pragma unroll
    for (int r = 0; r < 4; r++) {
        int h = r*256 + tid;
        float y = (hv[r] - mu) * rstd * ln_g[h] + ln_b[h];
        fp += y * W_fin[h];
    }
    red[tid] = fp; __syncthreads();
    for (int off = 128; off > 0; off >>= 1) {
        if (tid < off) red[tid] += red[tid + off];
        __syncthreads();
    }
    if (tid == 0) out[OFF_FIN + b] = red[0] + b_fin[0];
}

// ---------------------------------------------------------------------------
extern "C" void kernel_launch(void* const* d_in, const int* in_sizes, int n_in,
                              void* d_out, int out_size)
{
    const float* x      = (const float*)d_in[0];
    const float* h0     = (const float*)d_in[1];
    const float* c0     = (const float*)d_in[2];
    const float* enc    = (const float*)d_in[3];
    const float* W_enc  = (const float*)d_in[4];
    const float* W_dec  = (const float*)d_in[5];
    const float* w_val  = (const float*)d_in[6];
    const float* W_gate = (const float*)d_in[7];
    const float* events = (const float*)d_in[8];
    const float* W_ih   = (const float*)d_in[9];
    const float* W_hh   = (const float*)d_in[10];
    const float* b_ih   = (const float*)d_in[11];
    const float* b_hh   = (const float*)d_in[12];
    const float* ln_g   = (const float*)d_in[13];
    const float* ln_b   = (const float*)d_in[14];
    const float* W_fin  = (const float*)d_in[15];
    const float* b_fin  = (const float*)d_in[16];
    float* out = (float*)d_out;

    void* p;
    cudaGetSymbolAddress(&p, g_dec_proj); float* dec_proj = (float*)p;
    cudaGetSymbolAddress(&p, g_context);  float* context  = (float*)p;
    cudaGetSymbolAddress(&p, g_gates);    float* gates    = (float*)p;

    cudaFuncSetAttribute(k_attn_tc, cudaFuncAttributeMaxDynamicSharedMemorySize, ATTN_SMEM);

    k_zero<<<128, 256>>>();

    // dec_proj = h0 @ W_dec^T   (tensor cores, write mode)
    k_tc64<<<H / 128, 256>>>(h0, W_dec, H, nullptr, nullptr, 0, dec_proj, H, 0);

    // fused scores via mma.sync tf32 + cp.async pipeline
    k_attn_tc<<<dim3(H / BN, B * S / BM), 256, ATTN_SMEM>>>(enc, W_enc, w_val);

    k_softmax<<<B, 256>>>(out);
    k_context<<<dim3(B, H / 256), 256>>>(enc, out);
    k_sim<<<B, 320>>>(events, W_gate, out);

    k_gates_init<<<dim3(B, 16), 256>>>(x, W_ih, b_ih, b_hh);
    // gates += context @ W_ih[:, :1024]^T + h0 @ W_hh^T   (fused, accumulate)
    k_tc64<<<G4 / 128, 256>>>(context, W_ih, LSTM_IN, h0, W_hh, H, gates, G4, 1);

    k_lstm_final<<<B, 256>>>(c0, ln_g, ln_b, W_fin, b_fin, out);
}

// round 5
// speedup vs baseline: 1.0084x; 1.0084x over previous
#include <cuda_runtime.h>
#include <math.h>
#include <stdint.h>

#define B 64
#define S 512
#define H 1024
#define E 10
#define G4 4096
#define LSTM_IN 1035

// output packing offsets (flattened pytree order)
#define OFF_FIN 0
#define OFF_H   64
#define OFF_C   (64 + B*H)
#define OFF_A   (64 + 2*B*H)
#define OFF_S   (64 + 2*B*H + B*S)

// attn tiling: block 128(bs) x 128(g), BK=32, 3-stage cp.async pipeline
#define BM 128
#define BN 128
#define BK 32
#define NITER (H / BK)              // 32
#define PADK 36                      // floats per smem row (pad 32->36, 144 B)
#define A_STAGE (BM * PADK * 4)      // 18432 B
#define B_STAGE (BN * PADK * 4)      // 18432 B
#define STAGE   (A_STAGE + B_STAGE)  // 36864 B
#define NSTAGE 3
#define R_DP (NSTAGE * STAGE)        // 110592
#define R_WV (R_DP + BN * 4)
#define ATTN_SMEM (R_WV + BN * 4)    // 111616 B (~109 KB) -> 2 CTAs/SM

// scratch (no allocation allowed)
__device__ float g_dec_proj[B*H];
__device__ float g_scores[B*S];
__device__ float g_context[B*H];
__device__ float g_gates[B*G4];
__device__ float g_sim[B*E];

__device__ __forceinline__ float sigmoidf_(float x) { return 1.f / (1.f + expf(-x)); }

__device__ __forceinline__ uint32_t smem_u32(const void* p) {
    uint32_t a;
    asm("{ .reg .u64 t; cvta.to.shared.u64 t, %1; cvt.u32.u64 %0, t; }" : "=r"(a) : "l"(p));
    return a;
}

__device__ __forceinline__ void cp_async16(uint32_t dst, const void* src) {
    asm volatile("cp.async.cg.shared.global [%0], [%1], 16;" :: "r"(dst), "l"(src));
}
#define CP_COMMIT() asm volatile("cp.async.commit_group;" ::: "memory")

// raw fp32 operands: HMMA.TF32 truncates low mantissa bits in hardware (verified R4)
__device__ __forceinline__ void mma_tf32(float c[4], const uint32_t a[4], const uint32_t b[2]) {
    asm volatile(
        "mma.sync.aligned.m16n8k8.row.col.f32.tf32.tf32.f32 "
        "{%0,%1,%2,%3}, {%4,%5,%6,%7}, {%8,%9}, {%0,%1,%2,%3};\n"
        : "+f"(c[0]), "+f"(c[1]), "+f"(c[2]), "+f"(c[3])
        : "r"(a[0]), "r"(a[1]), "r"(a[2]), "r"(a[3]), "r"(b[0]), "r"(b[1]));
}

// ---------------------------------------------------------------------------
__global__ void k_zero() {
    int i = blockIdx.x * blockDim.x + threadIdx.x;
    if (i < B*S) g_scores[i] = 0.f;
}

// ---------------------------------------------------------------------------
// Fused attention-score GEMM via mma.sync tf32 + cp.async 3-stage pipeline.
//   scores[row] += sum_g w_val[g] * tanh(dec_proj[b,g] + enc[row,:] . W_enc[g,:])
// Block tile 128 x 128, 8 warps as 2M x 4N (warp tile 64x32). 2 CTAs/SM.
// grid = (H/BN = 8 [g fastest for L2 reuse of enc], B*S/BM = 256)
// ---------------------------------------------------------------------------
__global__ void __launch_bounds__(256, 2) k_attn_tc(
    const float* __restrict__ enc,
    const float* __restrict__ Wenc,
    const float* __restrict__ w_val)
{
    extern __shared__ char smem[];
    const uint32_t sb = smem_u32(smem);
    const int tid = threadIdx.x;
    const int lane = tid & 31, warp = tid >> 5;
    const int warpM = warp & 1, warpN = warp >> 1;
    const int group = lane >> 2, tid4 = lane & 3;

    const int gBase   = blockIdx.x * BN;
    const int rowBase = blockIdx.y * BM;
    const int b = rowBase / S;

    float* dp_s = (float*)(smem + R_DP);
    float* wv_s = (float*)(smem + R_WV);
    if (tid < BN) {
        dp_s[tid] = g_dec_proj[b*H + gBase + tid];
        wv_s[tid] = w_val[gBase + tid];
    }

    const float* Ag = enc  + (size_t)rowBase * H;
    const float* Bg = Wenc + (size_t)gBase   * H;

    auto issue = [&](int it, int stg) {
        uint32_t sa  = sb + stg * STAGE;
        uint32_t sbB = sa + A_STAGE;
        int k0 = it * BK;
#pragma unroll
        for (int i = 0; i < 4; i++) {            // A: 128 rows x 8 chunks of 16B
            int c = tid + 256 * i;
            int r = c >> 3, col = c & 7;
            cp_async16(sa + r * (PADK*4) + col * 16, Ag + (size_t)r * H + k0 + col * 4);
        }
#pragma unroll
        for (int i = 0; i < 4; i++) {            // B: 128 rows x 8 chunks of 16B
            int c = tid + 256 * i;
            int r = c >> 3, col = c & 7;
            cp_async16(sbB + r * (PADK*4) + col * 16, Bg + (size_t)r * H + k0 + col * 4);
        }
        CP_COMMIT();
    };

    float acc[4][4][4];
#pragma unroll
    for (int mi = 0; mi < 4; mi++)
#pragma unroll
        for (int ni = 0; ni < 4; ni++)
#pragma unroll
            for (int q = 0; q < 4; q++) acc[mi][ni][q] = 0.f;

    issue(0, 0);
    issue(1, 1);

    for (int it = 0; it < NITER; it++) {
        if (it < NITER - 1) { asm volatile("cp.async.wait_group 1;" ::: "memory"); }
        else                { asm volatile("cp.async.wait_group 0;" ::: "memory"); }
        __syncthreads();
        if (it + 2 < NITER) issue(it + 2, (it + 2) % NSTAGE);

        const float* As = (const float*)(smem + (it % NSTAGE) * STAGE);
        const float* Bs = (const float*)(smem + (it % NSTAGE) * STAGE + A_STAGE);

#pragma unroll
        for (int k8 = 0; k8 < 4; k8++) {
            int kk = k8 * 8;
            uint32_t afr[4][4], bfr[4][2];
#pragma unroll
            for (int mi = 0; mi < 4; mi++) {
                int m = warpM*64 + mi*16 + group;
                afr[mi][0] = __float_as_uint(As[(m    )*PADK + kk + tid4    ]);
                afr[mi][1] = __float_as_uint(As[(m + 8)*PADK + kk + tid4    ]);
                afr[mi][2] = __float_as_uint(As[(m    )*PADK + kk + tid4 + 4]);
                afr[mi][3] = __float_as_uint(As[(m + 8)*PADK + kk + tid4 + 4]);
            }
#pragma unroll
            for (int ni = 0; ni < 4; ni++) {
                int n = warpN*32 + ni*8 + group;
                bfr[ni][0] = __float_as_uint(Bs[n*PADK + kk + tid4    ]);
                bfr[ni][1] = __float_as_uint(Bs[n*PADK + kk + tid4 + 4]);
            }
#pragma unroll
            for (int mi = 0; mi < 4; mi++)
#pragma unroll
                for (int ni = 0; ni < 4; ni++)
                    mma_tf32(acc[mi][ni], afr[mi], bfr[ni]);
        }
        __syncthreads();
    }

    // epilogue: tanh + w_val dot over warp's 32 g-cols, quad shfl reduce, atomic
#pragma unroll
    for (int mi = 0; mi < 4; mi++) {
        float p0 = 0.f, p1 = 0.f;
#pragma unroll
        for (int ni = 0; ni < 4; ni++)
#pragma unroll
            for (int q = 0; q < 2; q++) {
                int g = warpN*32 + ni*8 + 2*tid4 + q;
                float wv = wv_s[g], dp = dp_s[g];
                p0 += wv * tanhf(acc[mi][ni][q    ] + dp);
                p1 += wv * tanhf(acc[mi][ni][2 + q] + dp);
            }
        p0 += __shfl_down_sync(0xffffffffu, p0, 2, 4);
        p0 += __shfl_down_sync(0xffffffffu, p0, 1, 4);
        p1 += __shfl_down_sync(0xffffffffu, p1, 2, 4);
        p1 += __shfl_down_sync(0xffffffffu, p1, 1, 4);
        if (tid4 == 0) {
            int row = rowBase + warpM*64 + mi*16 + group;
            atomicAdd(&g_scores[row    ], p0);
            atomicAdd(&g_scores[row + 8], p1);
        }
    }
}

// ---------------------------------------------------------------------------
// Small 64-row GEMM on tensor cores:
//   C[64, N] (+)= A0[64,1024] @ W0[:, :1024]^T  (+ A1[64,1024] @ W1[:, :1024]^T)
// Block 64x128, 8 warps as 2M x 4N (warp tile 32x32). No split-K, no atomics.
// ---------------------------------------------------------------------------
__global__ void __launch_bounds__(256) k_tc64(
    const float* __restrict__ A0, const float* __restrict__ W0, int ldw0,
    const float* __restrict__ A1, const float* __restrict__ W1, int ldw1,
    float* __restrict__ C, int ldc, int addC)
{
    __shared__ float As[64 * PADK];
    __shared__ float Ws[128 * PADK];
    const int tid = threadIdx.x;
    const int lane = tid & 31, warp = tid >> 5;
    const int warpM = warp & 1, warpN = warp >> 1;
    const int group = lane >> 2, tid4 = lane & 3;
    const int nBase = blockIdx.x * 128;

    float acc[2][4][4];
#pragma unroll
    for (int mi = 0; mi < 2; mi++)
#pragma unroll
        for (int ni = 0; ni < 4; ni++)
#pragma unroll
            for (int q = 0; q < 4; q++) acc[mi][ni][q] = 0.f;

    for (int src = 0; src < 2; src++) {
        const float* A = src ? A1 : A0;
        const float* W = src ? W1 : W0;
        int ldw = src ? ldw1 : ldw0;
        if (A == nullptr) break;

        for (int k0 = 0; k0 < H; k0 += BK) {
#pragma unroll
            for (int i = 0; i < 8; i++) {        // A: 64x32 floats
                int e = tid + 256 * i;
                As[(e >> 5) * PADK + (e & 31)] = A[(size_t)(e >> 5) * H + k0 + (e & 31)];
            }
#pragma unroll
            for (int i = 0; i < 16; i++) {       // W: 128x32 floats
                int e = tid + 256 * i;
                Ws[(e >> 5) * PADK + (e & 31)] = W[(size_t)(nBase + (e >> 5)) * ldw + k0 + (e & 31)];
            }
            __syncthreads();
#pragma unroll
            for (int k8 = 0; k8 < 4; k8++) {
                int kk = k8 * 8;
                uint32_t afr[2][4], bfr[4][2];
#pragma unroll
                for (int mi = 0; mi < 2; mi++) {
                    int m = warpM*32 + mi*16 + group;
                    afr[mi][0] = __float_as_uint(As[(m    )*PADK + kk + tid4    ]);
                    afr[mi][1] = __float_as_uint(As[(m + 8)*PADK + kk + tid4    ]);
                    afr[mi][2] = __float_as_uint(As[(m    )*PADK + kk + tid4 + 4]);
                    afr[mi][3] = __float_as_uint(As[(m + 8)*PADK + kk + tid4 + 4]);
                }
#pragma unroll
                for (int ni = 0; ni < 4; ni++) {
                    int n = warpN*32 + ni*8 + group;
                    bfr[ni][0] = __float_as_uint(Ws[n*PADK + kk + tid4    ]);
                    bfr[ni][1] = __float_as_uint(Ws[n*PADK + kk + tid4 + 4]);
                }
#pragma unroll
                for (int mi = 0; mi < 2; mi++)
#pragma unroll
                    for (int ni = 0; ni < 4; ni++)
                        mma_tf32(acc[mi][ni], afr[mi], bfr[ni]);
            }
            __syncthreads();
        }
    }

#pragma unroll
    for (int mi = 0; mi < 2; mi++)
#pragma unroll
        for (int ni = 0; ni < 4; ni++) {
            int row = warpM*32 + mi*16 + group;
            int col = nBase + warpN*32 + ni*8 + 2*tid4;
            float v0 = acc[mi][ni][0], v1 = acc[mi][ni][1];
            float v2 = acc[mi][ni][2], v3 = acc[mi][ni][3];
            if (addC) {
                v0 += C[(size_t)row*ldc + col];       v1 += C[(size_t)row*ldc + col + 1];
                v2 += C[(size_t)(row+8)*ldc + col];   v3 += C[(size_t)(row+8)*ldc + col + 1];
            }
            C[(size_t)row*ldc + col]         = v0;
            C[(size_t)row*ldc + col + 1]     = v1;
            C[(size_t)(row+8)*ldc + col]     = v2;
            C[(size_t)(row+8)*ldc + col + 1] = v3;
        }
}

// ---------------------------------------------------------------------------
__global__ void k_softmax(float* __restrict__ out)
{
    int b = blockIdx.x, tid = threadIdx.x;
    __shared__ float red[256];
    float s0 = g_scores[b*S + tid];
    float s1 = g_scores[b*S + 256 + tid];
    red[tid] = fmaxf(s0, s1);
    __syncthreads();
    for (int off = 128; off > 0; off >>= 1) {
        if (tid < off) red[tid] = fmaxf(red[tid], red[tid + off]);
        __syncthreads();
    }
    float m = red[0];
    __syncthreads();
    float e0 = expf(s0 - m), e1 = expf(s1 - m);
    red[tid] = e0 + e1;
    __syncthreads();
    for (int off = 128; off > 0; off >>= 1) {
        if (tid < off) red[tid] += red[tid + off];
        __syncthreads();
    }
    float inv = 1.f / red[0];
    out[OFF_A + b*S + tid]       = e0 * inv;
    out[OFF_A + b*S + 256 + tid] = e1 * inv;
}

// ---------------------------------------------------------------------------
__global__ void k_context(const float* __restrict__ enc, const float* __restrict__ out)
{
    int b = blockIdx.x;
    int h = blockIdx.y * 256 + threadIdx.x;
    __shared__ float w[S];
    for (int s = threadIdx.x; s < S; s += 256) w[s] = out[OFF_A + b*S + s];
    __syncthreads();
    const float* p = enc + (size_t)b * S * H + h;
    float a0 = 0.f, a1 = 0.f, a2 = 0.f, a3 = 0.f;
#pragma unroll 4
    for (int s = 0; s < S; s += 4) {
        a0 += w[s]     * p[(size_t)s * H];
        a1 += w[s + 1] * p[(size_t)(s + 1) * H];
        a2 += w[s + 2] * p[(size_t)(s + 2) * H];
        a3 += w[s + 3] * p[(size_t)(s + 3) * H];
    }
    g_context[b*H + h] = (a0 + a1) + (a2 + a3);
}

// ---------------------------------------------------------------------------
__global__ void k_sim(const float* __restrict__ events,
                      const float* __restrict__ W_gate,
                      float* __restrict__ out)
{
    int b = blockIdx.x;
    int tid = threadIdx.x, warp = tid >> 5, lane = tid & 31;
    __shared__ float t[E];
    if (warp < E) {
        float acc = 0.f;
        for (int h = lane; h < H; h += 32)
            acc += g_context[b*H + h] * events[warp*H + h];
#pragma unroll
        for (int off = 16; off > 0; off >>= 1)
            acc += __shfl_down_sync(0xffffffffu, acc, off);
        if (lane == 0) t[warp] = acc;
    }
    __syncthreads();
    if (tid < E) {
        float s = 0.f;
#pragma unroll
        for (int e = 0; e < E; e++) s += t[e] * W_gate[tid*E + e];
        g_sim[b*E + tid] = s;
        out[OFF_S + b*E + tid] = s;
    }
}

// ---------------------------------------------------------------------------
__global__ void k_gates_init(const float* __restrict__ x,
                             const float* __restrict__ W_ih,
                             const float* __restrict__ b_ih,
                             const float* __restrict__ b_hh)
{
    int b = blockIdx.x;
    int j = blockIdx.y * 256 + threadIdx.x;
    const float* wr = W_ih + (size_t)j * LSTM_IN;
    float v = b_ih[j] + b_hh[j] + x[b] * wr[1034];
#pragma unroll
    for (int e = 0; e < E; e++) v += g_sim[b*E + e] * wr[1024 + e];
    g_gates[b*G4 + j] = v;
}

// ---------------------------------------------------------------------------
__global__ void k_lstm_final(const float* __restrict__ c0,
                             const float* __restrict__ ln_g,
                             const float* __restrict__ ln_b,
                             const float* __restrict__ W_fin,
                             const float* __restrict__ b_fin,
                             float* __restrict__ out)
{
    int b = blockIdx.x, tid = threadIdx.x;
    __shared__ float red[256];
    float hv[4];
    float sum = 0.f;
#pragma unroll
    for (int r = 0; r < 4; r++) {
        int h = r*256 + tid;
        float ig = g_gates[b*G4 + h];
        float fg = g_gates[b*G4 + 1024 + h];
        float gg = g_gates[b*G4 + 2048 + h];
        float og = g_gates[b*G4 + 3072 + h];
        float cn = sigmoidf_(fg) * c0[b*H + h] + sigmoidf_(ig) * tanhf(gg);
        float hn = sigmoidf_(og) * tanhf(cn);
        out[OFF_H + b*H + h] = hn;
        out[OFF_C + b*H + h] = cn;
        hv[r] = hn;
        sum += hn;
    }
    red[tid] = sum; __syncthreads();
    for (int off = 128; off > 0; off >>= 1) {
        if (tid < off) red[tid] += red[tid + off];
        __syncthreads();
    }
    float mu = red[0] * (1.f / H);
    __syncthreads();
    float sq = 0.f;
#pragma unroll
    for (int r = 0; r < 4; r++) { float d = hv[r] - mu; sq += d * d; }
    red[tid] = sq; __syncthreads();
    for (int off = 128; off > 0; off >>= 1) {
        if (tid < off) red[tid] += red[tid + off];
        __syncthreads();
    }
    float rstd = rsqrtf(red[0] * (1.f / H) + 1e-5f);
    __syncthreads();
    float fp = 0.f;
#pragma unroll
    for (int r = 0; r < 4; r++) {
        int h = r*256 + tid;
        float y = (hv[r] - mu) * rstd * ln_g[h] + ln_b[h];
        fp += y * W_fin[h];
    }
    red[tid] = fp; __syncthreads();
    for (int off = 128; off > 0; off >>= 1) {
        if (tid < off) red[tid] += red[tid + off];
        __syncthreads();
    }
    if (tid == 0) out[OFF_FIN + b] = red[0] + b_fin[0];
}

// ---------------------------------------------------------------------------
extern "C" void kernel_launch(void* const* d_in, const int* in_sizes, int n_in,
                              void* d_out, int out_size)
{
    const float* x      = (const float*)d_in[0];
    const float* h0     = (const float*)d_in[1];
    const float* c0     = (const float*)d_in[2];
    const float* enc    = (const float*)d_in[3];
    const float* W_enc  = (const float*)d_in[4];
    const float* W_dec  = (const float*)d_in[5];
    const float* w_val  = (const float*)d_in[6];
    const float* W_gate = (const float*)d_in[7];
    const float* events = (const float*)d_in[8];
    const float* W_ih   = (const float*)d_in[9];
    const float* W_hh   = (const float*)d_in[10];
    const float* b_ih   = (const float*)d_in[11];
    const float* b_hh   = (const float*)d_in[12];
    const float* ln_g   = (const float*)d_in[13];
    const float* ln_b   = (const float*)d_in[14];
    const float* W_fin  = (const float*)d_in[15];
    const float* b_fin  = (const float*)d_in[16];
    float* out = (float*)d_out;

    void* p;
    cudaGetSymbolAddress(&p, g_dec_proj); float* dec_proj = (float*)p;
    cudaGetSymbolAddress(&p, g_context);  float* context  = (float*)p;
    cudaGetSymbolAddress(&p, g_gates);    float* gates    = (float*)p;

    cudaFuncSetAttribute(k_attn_tc, cudaFuncAttributeMaxDynamicSharedMemorySize, ATTN_SMEM);

    k_zero<<<128, 256>>>();

    // dec_proj = h0 @ W_dec^T   (tensor cores, write mode)
    k_tc64<<<H / 128, 256>>>(h0, W_dec, H, nullptr, nullptr, 0, dec_proj, H, 0);

    // fused scores via mma.sync tf32 + cp.async pipeline (R2 geometry)
    k_attn_tc<<<dim3(H / BN, B * S / BM), 256, ATTN_SMEM>>>(enc, W_enc, w_val);

    k_softmax<<<B, 256>>>(out);
    k_context<<<dim3(B, H / 256), 256>>>(enc, out);
    k_sim<<<B, 320>>>(events, W_gate, out);

    k_gates_init<<<dim3(B, 16), 256>>>(x, W_ih, b_ih, b_hh);
    // gates += context @ W_ih[:, :1024]^T + h0 @ W_hh^T   (fused, accumulate)
    k_tc64<<<G4 / 128, 256>>>(context, W_ih, LSTM_IN, h0, W_hh, H, gates, G4, 1);

    k_lstm_final<<<B, 256>>>(c0, ln_g, ln_b, W_fin, b_fin, out);
}

// round 6
// speedup vs baseline: 1.2749x; 1.2642x over previous
#include <cuda_runtime.h>
#include <cuda_fp16.h>
#include <math.h>
#include <stdint.h>

#define B 64
#define S 512
#define H 1024
#define E 10
#define G4 4096
#define LSTM_IN 1035

// output packing offsets (flattened pytree order)
#define OFF_FIN 0
#define OFF_H   64
#define OFF_C   (64 + B*H)
#define OFF_A   (64 + 2*B*H)
#define OFF_S   (64 + 2*B*H + B*S)

// attn tiling: block 128(bs) x 128(g), BK=32 (halves), 3-stage cp.async
#define BM 128
#define BN 128
#define BK 32
#define NITER (H / BK)            // 32
#define PADH 40                    // halfs per smem row (pad 32->40, 80 B)
#define A_ST (BM * PADH * 2)       // 10240 B
#define B_ST (BN * PADH * 2)       // 10240 B
#define STG  (A_ST + B_ST)         // 20480 B
#define NST 3
#define R_DP (NST * STG)           // 61440
#define R_WV (R_DP + BN * 4)
#define ATTN_SMEM (R_WV + BN * 4)  // 62464 B -> 2 CTAs/SM

#define PADK 36                    // fp32 pad for k_tc64

// scratch (no allocation allowed)
__device__ float g_dec_proj[B*H];
__device__ float g_scores[B*S];
__device__ float g_context[B*H];
__device__ float g_gates[B*G4];
__device__ float g_sim[B*E];
__device__ __half g_enc_h[B*S*H];    // 67 MB fp16 mirror of enc
__device__ __half g_wenc_h[H*H];     // 2 MB fp16 mirror of W_enc

__device__ __forceinline__ float sigmoidf_(float x) { return 1.f / (1.f + expf(-x)); }

__device__ __forceinline__ uint32_t smem_u32(const void* p) {
    uint32_t a;
    asm("{ .reg .u64 t; cvta.to.shared.u64 t, %1; cvt.u32.u64 %0, t; }" : "=r"(a) : "l"(p));
    return a;
}

__device__ __forceinline__ void cp_async16(uint32_t dst, const void* src) {
    asm volatile("cp.async.cg.shared.global [%0], [%1], 16;" :: "r"(dst), "l"(src));
}
#define CP_COMMIT() asm volatile("cp.async.commit_group;" ::: "memory")

__device__ __forceinline__ void mma_f16(float c[4], const uint32_t a[4], const uint32_t b[2]) {
    asm volatile(
        "mma.sync.aligned.m16n8k16.row.col.f32.f16.f16.f32 "
        "{%0,%1,%2,%3}, {%4,%5,%6,%7}, {%8,%9}, {%0,%1,%2,%3};\n"
        : "+f"(c[0]), "+f"(c[1]), "+f"(c[2]), "+f"(c[3])
        : "r"(a[0]), "r"(a[1]), "r"(a[2]), "r"(a[3]), "r"(b[0]), "r"(b[1]));
}

// raw fp32 into HMMA.TF32 (HW-truncated) for small GEMMs
__device__ __forceinline__ void mma_tf32(float c[4], const uint32_t a[4], const uint32_t b[2]) {
    asm volatile(
        "mma.sync.aligned.m16n8k8.row.col.f32.tf32.tf32.f32 "
        "{%0,%1,%2,%3}, {%4,%5,%6,%7}, {%8,%9}, {%0,%1,%2,%3};\n"
        : "+f"(c[0]), "+f"(c[1]), "+f"(c[2]), "+f"(c[3])
        : "r"(a[0]), "r"(a[1]), "r"(a[2]), "r"(a[3]), "r"(b[0]), "r"(b[1]));
}

// ---------------------------------------------------------------------------
__global__ void k_zero() {
    int i = blockIdx.x * blockDim.x + threadIdx.x;
    if (i < B*S) g_scores[i] = 0.f;
}

// fp32 -> fp16 vector convert (RN)
__global__ void k_cvt(const float* __restrict__ src, __half* __restrict__ dst, int n4) {
    int i = blockIdx.x * blockDim.x + threadIdx.x;
    if (i < n4) {
        float4 v = ((const float4*)src)[i];
        __half2 h0 = __floats2half2_rn(v.x, v.y);
        __half2 h1 = __floats2half2_rn(v.z, v.w);
        ((__half2*)dst)[2*i]     = h0;
        ((__half2*)dst)[2*i + 1] = h1;
    }
}

// ---------------------------------------------------------------------------
// fp16 fused attention-score GEMM via mma.sync m16n8k16 + cp.async 3-stage.
//   scores[row] += sum_g w_val[g] * tanh(dec_proj[b,g] + enc[row,:] . W_enc[g,:])
// Block tile 128 x 128, 8 warps as 2M x 4N (warp tile 64x32). 2 CTAs/SM.
// grid = (H/BN = 8 [g fastest, L2 reuse of enc_h], B*S/BM = 256)
// ---------------------------------------------------------------------------
__global__ void __launch_bounds__(256, 2) k_attn_f16(
    const __half* __restrict__ ench,
    const __half* __restrict__ wench,
    const float* __restrict__ w_val)
{
    extern __shared__ char smem[];
    const uint32_t sb = smem_u32(smem);
    const int tid = threadIdx.x;
    const int lane = tid & 31, warp = tid >> 5;
    const int warpM = warp & 1, warpN = warp >> 1;
    const int group = lane >> 2, tid4 = lane & 3;

    const int gBase   = blockIdx.x * BN;
    const int rowBase = blockIdx.y * BM;
    const int b = rowBase / S;

    float* dp_s = (float*)(smem + R_DP);
    float* wv_s = (float*)(smem + R_WV);
    if (tid < BN) {
        dp_s[tid] = g_dec_proj[b*H + gBase + tid];
        wv_s[tid] = w_val[gBase + tid];
    }

    const __half* Ah = ench  + (size_t)rowBase * H;
    const __half* Bh = wench + (size_t)gBase   * H;

    auto issue = [&](int it, int stg) {
        uint32_t sa  = sb + stg * STG;
        uint32_t sbB = sa + A_ST;
        int k0 = it * BK;
#pragma unroll
        for (int i = 0; i < 2; i++) {        // A: 128 rows x 4 chunks of 16B
            int c = tid + 256 * i;
            int r = c >> 2, col = c & 3;
            cp_async16(sa + r * 80 + col * 16, Ah + (size_t)r * H + k0 + col * 8);
        }
#pragma unroll
        for (int i = 0; i < 2; i++) {        // B: 128 rows x 4 chunks of 16B
            int c = tid + 256 * i;
            int r = c >> 2, col = c & 3;
            cp_async16(sbB + r * 80 + col * 16, Bh + (size_t)r * H + k0 + col * 8);
        }
        CP_COMMIT();
    };

    float acc[4][4][4];
#pragma unroll
    for (int mi = 0; mi < 4; mi++)
#pragma unroll
        for (int ni = 0; ni < 4; ni++)
#pragma unroll
            for (int q = 0; q < 4; q++) acc[mi][ni][q] = 0.f;

    issue(0, 0);
    issue(1, 1);

    for (int it = 0; it < NITER; it++) {
        if (it < NITER - 1) { asm volatile("cp.async.wait_group 1;" ::: "memory"); }
        else                { asm volatile("cp.async.wait_group 0;" ::: "memory"); }
        __syncthreads();
        if (it + 2 < NITER) issue(it + 2, (it + 2) % NST);

        const uint32_t* As = (const uint32_t*)(smem + (it % NST) * STG);
        const uint32_t* Bs = (const uint32_t*)(smem + (it % NST) * STG + A_ST);

#pragma unroll
        for (int k16 = 0; k16 < 2; k16++) {
            const int kw = k16 * 8;          // word offset of this k16 block
            uint32_t afr[4][4], bfr[4][2];
#pragma unroll
            for (int mi = 0; mi < 4; mi++) {
                int m = warpM*64 + mi*16 + group;
                afr[mi][0] = As[(m    )*20 + kw + tid4    ];
                afr[mi][1] = As[(m + 8)*20 + kw + tid4    ];
                afr[mi][2] = As[(m    )*20 + kw + tid4 + 4];
                afr[mi][3] = As[(m + 8)*20 + kw + tid4 + 4];
            }
#pragma unroll
            for (int ni = 0; ni < 4; ni++) {
                int n = warpN*32 + ni*8 + group;
                bfr[ni][0] = Bs[n*20 + kw + tid4    ];
                bfr[ni][1] = Bs[n*20 + kw + tid4 + 4];
            }
#pragma unroll
            for (int mi = 0; mi < 4; mi++)
#pragma unroll
                for (int ni = 0; ni < 4; ni++)
                    mma_f16(acc[mi][ni], afr[mi], bfr[ni]);
        }
        __syncthreads();
    }

    // epilogue: tanh + w_val dot over warp's 32 g-cols, quad shfl reduce, atomic
#pragma unroll
    for (int mi = 0; mi < 4; mi++) {
        float p0 = 0.f, p1 = 0.f;
#pragma unroll
        for (int ni = 0; ni < 4; ni++)
#pragma unroll
            for (int q = 0; q < 2; q++) {
                int g = warpN*32 + ni*8 + 2*tid4 + q;
                float wv = wv_s[g], dp = dp_s[g];
                p0 += wv * tanhf(acc[mi][ni][q    ] + dp);
                p1 += wv * tanhf(acc[mi][ni][2 + q] + dp);
            }
        p0 += __shfl_down_sync(0xffffffffu, p0, 2, 4);
        p0 += __shfl_down_sync(0xffffffffu, p0, 1, 4);
        p1 += __shfl_down_sync(0xffffffffu, p1, 2, 4);
        p1 += __shfl_down_sync(0xffffffffu, p1, 1, 4);
        if (tid4 == 0) {
            int row = rowBase + warpM*64 + mi*16 + group;
            atomicAdd(&g_scores[row    ], p0);
            atomicAdd(&g_scores[row + 8], p1);
        }
    }
}

// ---------------------------------------------------------------------------
// Small 64-row GEMM on tensor cores (tf32):
//   C[64, N] (+)= A0[64,1024] @ W0[:, :1024]^T  (+ A1[64,1024] @ W1[:, :1024]^T)
// ---------------------------------------------------------------------------
__global__ void __launch_bounds__(256) k_tc64(
    const float* __restrict__ A0, const float* __restrict__ W0, int ldw0,
    const float* __restrict__ A1, const float* __restrict__ W1, int ldw1,
    float* __restrict__ C, int ldc, int addC)
{
    __shared__ float As[64 * PADK];
    __shared__ float Ws[128 * PADK];
    const int tid = threadIdx.x;
    const int lane = tid & 31, warp = tid >> 5;
    const int warpM = warp & 1, warpN = warp >> 1;
    const int group = lane >> 2, tid4 = lane & 3;
    const int nBase = blockIdx.x * 128;

    float acc[2][4][4];
#pragma unroll
    for (int mi = 0; mi < 2; mi++)
#pragma unroll
        for (int ni = 0; ni < 4; ni++)
#pragma unroll
            for (int q = 0; q < 4; q++) acc[mi][ni][q] = 0.f;

    for (int src = 0; src < 2; src++) {
        const float* A = src ? A1 : A0;
        const float* W = src ? W1 : W0;
        int ldw = src ? ldw1 : ldw0;
        if (A == nullptr) break;

        for (int k0 = 0; k0 < H; k0 += 32) {
#pragma unroll
            for (int i = 0; i < 8; i++) {
                int e = tid + 256 * i;
                As[(e >> 5) * PADK + (e & 31)] = A[(size_t)(e >> 5) * H + k0 + (e & 31)];
            }
#pragma unroll
            for (int i = 0; i < 16; i++) {
                int e = tid + 256 * i;
                Ws[(e >> 5) * PADK + (e & 31)] = W[(size_t)(nBase + (e >> 5)) * ldw + k0 + (e & 31)];
            }
            __syncthreads();
#pragma unroll
            for (int k8 = 0; k8 < 4; k8++) {
                int kk = k8 * 8;
                uint32_t afr[2][4], bfr[4][2];
#pragma unroll
                for (int mi = 0; mi < 2; mi++) {
                    int m = warpM*32 + mi*16 + group;
                    afr[mi][0] = __float_as_uint(As[(m    )*PADK + kk + tid4    ]);
                    afr[mi][1] = __float_as_uint(As[(m + 8)*PADK + kk + tid4    ]);
                    afr[mi][2] = __float_as_uint(As[(m    )*PADK + kk + tid4 + 4]);
                    afr[mi][3] = __float_as_uint(As[(m + 8)*PADK + kk + tid4 + 4]);
                }
#pragma unroll
                for (int ni = 0; ni < 4; ni++) {
                    int n = warpN*32 + ni*8 + group;
                    bfr[ni][0] = __float_as_uint(Ws[n*PADK + kk + tid4    ]);
                    bfr[ni][1] = __float_as_uint(Ws[n*PADK + kk + tid4 + 4]);
                }
#pragma unroll
                for (int mi = 0; mi < 2; mi++)
#pragma unroll
                    for (int ni = 0; ni < 4; ni++)
                        mma_tf32(acc[mi][ni], afr[mi], bfr[ni]);
            }
            __syncthreads();
        }
    }

#pragma unroll
    for (int mi = 0; mi < 2; mi++)
#pragma unroll
        for (int ni = 0; ni < 4; ni++) {
            int row = warpM*32 + mi*16 + group;
            int col = nBase + warpN*32 + ni*8 + 2*tid4;
            float v0 = acc[mi][ni][0], v1 = acc[mi][ni][1];
            float v2 = acc[mi][ni][2], v3 = acc[mi][ni][3];
            if (addC) {
                v0 += C[(size_t)row*ldc + col];       v1 += C[(size_t)row*ldc + col + 1];
                v2 += C[(size_t)(row+8)*ldc + col];   v3 += C[(size_t)(row+8)*ldc + col + 1];
            }
            C[(size_t)row*ldc + col]         = v0;
            C[(size_t)row*ldc + col + 1]     = v1;
            C[(size_t)(row+8)*ldc + col]     = v2;
            C[(size_t)(row+8)*ldc + col + 1] = v3;
        }
}

// ---------------------------------------------------------------------------
__global__ void k_softmax(float* __restrict__ out)
{
    int b = blockIdx.x, tid = threadIdx.x;
    __shared__ float red[256];
    float s0 = g_scores[b*S + tid];
    float s1 = g_scores[b*S + 256 + tid];
    red[tid] = fmaxf(s0, s1);
    __syncthreads();
    for (int off = 128; off > 0; off >>= 1) {
        if (tid < off) red[tid] = fmaxf(red[tid], red[tid + off]);
        __syncthreads();
    }
    float m = red[0];
    __syncthreads();
    float e0 = expf(s0 - m), e1 = expf(s1 - m);
    red[tid] = e0 + e1;
    __syncthreads();
    for (int off = 128; off > 0; off >>= 1) {
        if (tid < off) red[tid] += red[tid + off];
        __syncthreads();
    }
    float inv = 1.f / red[0];
    out[OFF_A + b*S + tid]       = e0 * inv;
    out[OFF_A + b*S + 256 + tid] = e1 * inv;
}

// ---------------------------------------------------------------------------
__global__ void k_context(const float* __restrict__ enc, const float* __restrict__ out)
{
    int b = blockIdx.x;
    int h = blockIdx.y * 256 + threadIdx.x;
    __shared__ float w[S];
    for (int s = threadIdx.x; s < S; s += 256) w[s] = out[OFF_A + b*S + s];
    __syncthreads();
    const float* p = enc + (size_t)b * S * H + h;
    float a0 = 0.f, a1 = 0.f, a2 = 0.f, a3 = 0.f;
#pragma unroll 4
    for (int s = 0; s < S; s += 4) {
        a0 += w[s]     * p[(size_t)s * H];
        a1 += w[s + 1] * p[(size_t)(s + 1) * H];
        a2 += w[s + 2] * p[(size_t)(s + 2) * H];
        a3 += w[s + 3] * p[(size_t)(s + 3) * H];
    }
    g_context[b*H + h] = (a0 + a1) + (a2 + a3);
}

// ---------------------------------------------------------------------------
__global__ void k_sim(const float* __restrict__ events,
                      const float* __restrict__ W_gate,
                      float* __restrict__ out)
{
    int b = blockIdx.x;
    int tid = threadIdx.x, warp = tid >> 5, lane = tid & 31;
    __shared__ float t[E];
    if (warp < E) {
        float acc = 0.f;
        for (int h = lane; h < H; h += 32)
            acc += g_context[b*H + h] * events[warp*H + h];
#pragma unroll
        for (int off = 16; off > 0; off >>= 1)
            acc += __shfl_down_sync(0xffffffffu, acc, off);
        if (lane == 0) t[warp] = acc;
    }
    __syncthreads();
    if (tid < E) {
        float s = 0.f;
#pragma unroll
        for (int e = 0; e < E; e++) s += t[e] * W_gate[tid*E + e];
        g_sim[b*E + tid] = s;
        out[OFF_S + b*E + tid] = s;
    }
}

// ---------------------------------------------------------------------------
__global__ void k_gates_init(const float* __restrict__ x,
                             const float* __restrict__ W_ih,
                             const float* __restrict__ b_ih,
                             const float* __restrict__ b_hh)
{
    int b = blockIdx.x;
    int j = blockIdx.y * 256 + threadIdx.x;
    const float* wr = W_ih + (size_t)j * LSTM_IN;
    float v = b_ih[j] + b_hh[j] + x[b] * wr[1034];
#pragma unroll
    for (int e = 0; e < E; e++) v += g_sim[b*E + e] * wr[1024 + e];
    g_gates[b*G4 + j] = v;
}

// ---------------------------------------------------------------------------
__global__ void k_lstm_final(const float* __restrict__ c0,
                             const float* __restrict__ ln_g,
                             const float* __restrict__ ln_b,
                             const float* __restrict__ W_fin,
                             const float* __restrict__ b_fin,
                             float* __restrict__ out)
{
    int b = blockIdx.x, tid = threadIdx.x;
    __shared__ float red[256];
    float hv[4];
    float sum = 0.f;
#pragma unroll
    for (int r = 0; r < 4; r++) {
        int h = r*256 + tid;
        float ig = g_gates[b*G4 + h];
        float fg = g_gates[b*G4 + 1024 + h];
        float gg = g_gates[b*G4 + 2048 + h];
        float og = g_gates[b*G4 + 3072 + h];
        float cn = sigmoidf_(fg) * c0[b*H + h] + sigmoidf_(ig) * tanhf(gg);
        float hn = sigmoidf_(og) * tanhf(cn);
        out[OFF_H + b*H + h] = hn;
        out[OFF_C + b*H + h] = cn;
        hv[r] = hn;
        sum += hn;
    }
    red[tid] = sum; __syncthreads();
    for (int off = 128; off > 0; off >>= 1) {
        if (tid < off) red[tid] += red[tid + off];
        __syncthreads();
    }
    float mu = red[0] * (1.f / H);
    __syncthreads();
    float sq = 0.f;
#pragma unroll
    for (int r = 0; r < 4; r++) { float d = hv[r] - mu; sq += d * d; }
    red[tid] = sq; __syncthreads();
    for (int off = 128; off > 0; off >>= 1) {
        if (tid < off) red[tid] += red[tid + off];
        __syncthreads();
    }
    float rstd = rsqrtf(red[0] * (1.f / H) + 1e-5f);
    __syncthreads();
    float fp = 0.f;
#pragma unroll
    for (int r = 0; r < 4; r++) {
        int h = r*256 + tid;
        float y = (hv[r] - mu) * rstd * ln_g[h] + ln_b[h];
        fp += y * W_fin[h];
    }
    red[tid] = fp; __syncthreads();
    for (int off = 128; off > 0; off >>= 1) {
        if (tid < off) red[tid] += red[tid + off];
        __syncthreads();
    }
    if (tid == 0) out[OFF_FIN + b] = red[0] + b_fin[0];
}

// ---------------------------------------------------------------------------
extern "C" void kernel_launch(void* const* d_in, const int* in_sizes, int n_in,
                              void* d_out, int out_size)
{
    const float* x      = (const float*)d_in[0];
    const float* h0     = (const float*)d_in[1];
    const float* c0     = (const float*)d_in[2];
    const float* enc    = (const float*)d_in[3];
    const float* W_enc  = (const float*)d_in[4];
    const float* W_dec  = (const float*)d_in[5];
    const float* w_val  = (const float*)d_in[6];
    const float* W_gate = (const float*)d_in[7];
    const float* events = (const float*)d_in[8];
    const float* W_ih   = (const float*)d_in[9];
    const float* W_hh   = (const float*)d_in[10];
    const float* b_ih   = (const float*)d_in[11];
    const float* b_hh   = (const float*)d_in[12];
    const float* ln_g   = (const float*)d_in[13];
    const float* ln_b   = (const float*)d_in[14];
    const float* W_fin  = (const float*)d_in[15];
    const float* b_fin  = (const float*)d_in[16];
    float* out = (float*)d_out;

    void* p;
    cudaGetSymbolAddress(&p, g_dec_proj); float*  dec_proj = (float*)p;
    cudaGetSymbolAddress(&p, g_context);  float*  context  = (float*)p;
    cudaGetSymbolAddress(&p, g_gates);    float*  gates    = (float*)p;
    cudaGetSymbolAddress(&p, g_enc_h);    __half* ench     = (__half*)p;
    cudaGetSymbolAddress(&p, g_wenc_h);   __half* wench    = (__half*)p;

    cudaFuncSetAttribute(k_attn_f16, cudaFuncAttributeMaxDynamicSharedMemorySize, ATTN_SMEM);

    k_zero<<<128, 256>>>();

    // fp16 mirrors of enc and W_enc
    k_cvt<<<(B*S*H/4 + 255)/256, 256>>>(enc, ench, B*S*H/4);
    k_cvt<<<(H*H/4 + 255)/256, 256>>>(W_enc, wench, H*H/4);

    // dec_proj = h0 @ W_dec^T (tf32 tensor cores)
    k_tc64<<<H / 128, 256>>>(h0, W_dec, H, nullptr, nullptr, 0, dec_proj, H, 0);

    // fused scores via fp16 mma.sync m16n8k16
    k_attn_f16<<<dim3(H / BN, B * S / BM), 256, ATTN_SMEM>>>(ench, wench, w_val);

    k_softmax<<<B, 256>>>(out);
    k_context<<<dim3(B, H / 256), 256>>>(enc, out);
    k_sim<<<B, 320>>>(events, W_gate, out);

    k_gates_init<<<dim3(B, 16), 256>>>(x, W_ih, b_ih, b_hh);
    // gates += context @ W_ih[:, :1024]^T + h0 @ W_hh^T
    k_tc64<<<G4 / 128, 256>>>(context, W_ih, LSTM_IN, h0, W_hh, H, gates, G4, 1);

    k_lstm_final<<<B, 256>>>(c0, ln_g, ln_b, W_fin, b_fin, out);
}

// round 7
// speedup vs baseline: 1.7776x; 1.3943x over previous
#include <cuda_runtime.h>
#include <cuda_fp16.h>
#include <math.h>
#include <stdint.h>

#define B 64
#define S 512
#define H 1024
#define E 10
#define G4 4096
#define LSTM_IN 1035

// output packing offsets (flattened pytree order)
#define OFF_FIN 0
#define OFF_H   64
#define OFF_C   (64 + B*H)
#define OFF_A   (64 + 2*B*H)
#define OFF_S   (64 + 2*B*H + B*S)

// attn tiling: block 128(bs) x 128(g), BK=32 (halves), 3-stage cp.async
#define BM 128
#define BN 128
#define BK 32
#define NITER (H / BK)            // 32
#define PADH 40                    // halfs per smem row (pad 32->40, 80 B)
#define A_ST (BM * PADH * 2)       // 10240 B
#define B_ST (BN * PADH * 2)       // 10240 B
#define STG  (A_ST + B_ST)         // 20480 B
#define NST 3
#define R_DP (NST * STG)           // 61440
#define R_WV (R_DP + BN * 4)
#define ATTN_SMEM (R_WV + BN * 4)  // 62464 B -> 2 CTAs/SM

#define PADK 36                    // fp32 pad for k_tc64
#define KCH 256                    // split-K chunk for k_tc64

// scratch (no allocation allowed)
__device__ float g_dec_proj[B*H];
__device__ float g_scores[B*S];
__device__ float g_context[B*H];
__device__ float g_gates[B*G4];
__device__ float g_sim[B*E];
__device__ __half g_enc_h[B*S*H];    // 67 MB fp16 mirror of enc
__device__ __half g_wenc_h[H*H];     // 2 MB fp16 mirror of W_enc

__device__ __forceinline__ float sigmoidf_(float x) { return 1.f / (1.f + expf(-x)); }

__device__ __forceinline__ uint32_t smem_u32(const void* p) {
    uint32_t a;
    asm("{ .reg .u64 t; cvta.to.shared.u64 t, %1; cvt.u32.u64 %0, t; }" : "=r"(a) : "l"(p));
    return a;
}

__device__ __forceinline__ uint32_t f2tf32(float x) {   // round-to-nearest tf32
    uint32_t r;
    asm("cvt.rna.tf32.f32 %0, %1;" : "=r"(r) : "f"(x));
    return r;
}

__device__ __forceinline__ void cp_async16(uint32_t dst, const void* src) {
    asm volatile("cp.async.cg.shared.global [%0], [%1], 16;" :: "r"(dst), "l"(src));
}
#define CP_COMMIT() asm volatile("cp.async.commit_group;" ::: "memory")

__device__ __forceinline__ void mma_f16(float c[4], const uint32_t a[4], const uint32_t b[2]) {
    asm volatile(
        "mma.sync.aligned.m16n8k16.row.col.f32.f16.f16.f32 "
        "{%0,%1,%2,%3}, {%4,%5,%6,%7}, {%8,%9}, {%0,%1,%2,%3};\n"
        : "+f"(c[0]), "+f"(c[1]), "+f"(c[2]), "+f"(c[3])
        : "r"(a[0]), "r"(a[1]), "r"(a[2]), "r"(a[3]), "r"(b[0]), "r"(b[1]));
}

__device__ __forceinline__ void mma_tf32(float c[4], const uint32_t a[4], const uint32_t b[2]) {
    asm volatile(
        "mma.sync.aligned.m16n8k8.row.col.f32.tf32.tf32.f32 "
        "{%0,%1,%2,%3}, {%4,%5,%6,%7}, {%8,%9}, {%0,%1,%2,%3};\n"
        : "+f"(c[0]), "+f"(c[1]), "+f"(c[2]), "+f"(c[3])
        : "r"(a[0]), "r"(a[1]), "r"(a[2]), "r"(a[3]), "r"(b[0]), "r"(b[1]));
}

// ---------------------------------------------------------------------------
__global__ void k_zero() {
    int i = blockIdx.x * blockDim.x + threadIdx.x;
    if (i < B*S) g_scores[i] = 0.f;
    if (i < B*H) g_dec_proj[i] = 0.f;
}

// fp32 -> fp16 vector convert (RN)
__global__ void k_cvt(const float* __restrict__ src, __half* __restrict__ dst, int n4) {
    int i = blockIdx.x * blockDim.x + threadIdx.x;
    if (i < n4) {
        float4 v = ((const float4*)src)[i];
        ((__half2*)dst)[2*i]     = __floats2half2_rn(v.x, v.y);
        ((__half2*)dst)[2*i + 1] = __floats2half2_rn(v.z, v.w);
    }
}

// ---------------------------------------------------------------------------
// fp16 fused attention-score GEMM via mma.sync m16n8k16 + cp.async 3-stage.
// Block tile 128 x 128, 8 warps as 2M x 4N (warp tile 64x32). 2 CTAs/SM.
// grid = (H/BN = 8 [g fastest, L2 reuse of enc_h], B*S/BM = 256)
// ---------------------------------------------------------------------------
__global__ void __launch_bounds__(256, 2) k_attn_f16(
    const __half* __restrict__ ench,
    const __half* __restrict__ wench,
    const float* __restrict__ w_val)
{
    extern __shared__ char smem[];
    const uint32_t sb = smem_u32(smem);
    const int tid = threadIdx.x;
    const int lane = tid & 31, warp = tid >> 5;
    const int warpM = warp & 1, warpN = warp >> 1;
    const int group = lane >> 2, tid4 = lane & 3;

    const int gBase   = blockIdx.x * BN;
    const int rowBase = blockIdx.y * BM;
    const int b = rowBase / S;

    float* dp_s = (float*)(smem + R_DP);
    float* wv_s = (float*)(smem + R_WV);
    if (tid < BN) {
        dp_s[tid] = g_dec_proj[b*H + gBase + tid];
        wv_s[tid] = w_val[gBase + tid];
    }

    const __half* Ah = ench  + (size_t)rowBase * H;
    const __half* Bh = wench + (size_t)gBase   * H;

    auto issue = [&](int it, int stg) {
        uint32_t sa  = sb + stg * STG;
        uint32_t sbB = sa + A_ST;
        int k0 = it * BK;
#pragma unroll
        for (int i = 0; i < 2; i++) {
            int c = tid + 256 * i;
            int r = c >> 2, col = c & 3;
            cp_async16(sa + r * 80 + col * 16, Ah + (size_t)r * H + k0 + col * 8);
        }
#pragma unroll
        for (int i = 0; i < 2; i++) {
            int c = tid + 256 * i;
            int r = c >> 2, col = c & 3;
            cp_async16(sbB + r * 80 + col * 16, Bh + (size_t)r * H + k0 + col * 8);
        }
        CP_COMMIT();
    };

    float acc[4][4][4];
#pragma unroll
    for (int mi = 0; mi < 4; mi++)
#pragma unroll
        for (int ni = 0; ni < 4; ni++)
#pragma unroll
            for (int q = 0; q < 4; q++) acc[mi][ni][q] = 0.f;

    issue(0, 0);
    issue(1, 1);

    for (int it = 0; it < NITER; it++) {
        if (it < NITER - 1) { asm volatile("cp.async.wait_group 1;" ::: "memory"); }
        else                { asm volatile("cp.async.wait_group 0;" ::: "memory"); }
        __syncthreads();
        if (it + 2 < NITER) issue(it + 2, (it + 2) % NST);

        const uint32_t* As = (const uint32_t*)(smem + (it % NST) * STG);
        const uint32_t* Bs = (const uint32_t*)(smem + (it % NST) * STG + A_ST);

#pragma unroll
        for (int k16 = 0; k16 < 2; k16++) {
            const int kw = k16 * 8;
            uint32_t afr[4][4], bfr[4][2];
#pragma unroll
            for (int mi = 0; mi < 4; mi++) {
                int m = warpM*64 + mi*16 + group;
                afr[mi][0] = As[(m    )*20 + kw + tid4    ];
                afr[mi][1] = As[(m + 8)*20 + kw + tid4    ];
                afr[mi][2] = As[(m    )*20 + kw + tid4 + 4];
                afr[mi][3] = As[(m + 8)*20 + kw + tid4 + 4];
            }
#pragma unroll
            for (int ni = 0; ni < 4; ni++) {
                int n = warpN*32 + ni*8 + group;
                bfr[ni][0] = Bs[n*20 + kw + tid4    ];
                bfr[ni][1] = Bs[n*20 + kw + tid4 + 4];
            }
#pragma unroll
            for (int mi = 0; mi < 4; mi++)
#pragma unroll
                for (int ni = 0; ni < 4; ni++)
                    mma_f16(acc[mi][ni], afr[mi], bfr[ni]);
        }
        __syncthreads();
    }

#pragma unroll
    for (int mi = 0; mi < 4; mi++) {
        float p0 = 0.f, p1 = 0.f;
#pragma unroll
        for (int ni = 0; ni < 4; ni++)
#pragma unroll
            for (int q = 0; q < 2; q++) {
                int g = warpN*32 + ni*8 + 2*tid4 + q;
                float wv = wv_s[g], dp = dp_s[g];
                p0 += wv * tanhf(acc[mi][ni][q    ] + dp);
                p1 += wv * tanhf(acc[mi][ni][2 + q] + dp);
            }
        p0 += __shfl_down_sync(0xffffffffu, p0, 2, 4);
        p0 += __shfl_down_sync(0xffffffffu, p0, 1, 4);
        p1 += __shfl_down_sync(0xffffffffu, p1, 2, 4);
        p1 += __shfl_down_sync(0xffffffffu, p1, 1, 4);
        if (tid4 == 0) {
            int row = rowBase + warpM*64 + mi*16 + group;
            atomicAdd(&g_scores[row    ], p0);
            atomicAdd(&g_scores[row + 8], p1);
        }
    }
}

// ---------------------------------------------------------------------------
// Split-K 64-row GEMM on tensor cores (tf32, RN-rounded operands):
//   C[64, N] += A[64, 1024] @ W[N, ldw]^T   accumulated atomically.
// grid = (N/128, nChunks).  Chunk >= 4 selects source 1 (A1/W1).
// ---------------------------------------------------------------------------
__global__ void __launch_bounds__(256) k_tc64(
    const float* __restrict__ A0, const float* __restrict__ W0, int ldw0,
    const float* __restrict__ A1, const float* __restrict__ W1, int ldw1,
    float* __restrict__ C, int ldc)
{
    __shared__ float As[64 * PADK];
    __shared__ float Ws[128 * PADK];
    const int tid = threadIdx.x;
    const int lane = tid & 31, warp = tid >> 5;
    const int warpM = warp & 1, warpN = warp >> 1;
    const int group = lane >> 2, tid4 = lane & 3;
    const int nBase = blockIdx.x * 128;
    const int chunk = blockIdx.y;

    const float* A = (chunk >= 4) ? A1 : A0;
    const float* W = (chunk >= 4) ? W1 : W0;
    const int ldw  = (chunk >= 4) ? ldw1 : ldw0;
    const int kb = (chunk & 3) * KCH;

    float acc[2][4][4];
#pragma unroll
    for (int mi = 0; mi < 2; mi++)
#pragma unroll
        for (int ni = 0; ni < 4; ni++)
#pragma unroll
            for (int q = 0; q < 4; q++) acc[mi][ni][q] = 0.f;

    for (int k0 = kb; k0 < kb + KCH; k0 += 32) {
#pragma unroll
        for (int i = 0; i < 8; i++) {
            int e = tid + 256 * i;
            As[(e >> 5) * PADK + (e & 31)] =
                __uint_as_float(f2tf32(A[(size_t)(e >> 5) * H + k0 + (e & 31)]));
        }
#pragma unroll
        for (int i = 0; i < 16; i++) {
            int e = tid + 256 * i;
            Ws[(e >> 5) * PADK + (e & 31)] =
                __uint_as_float(f2tf32(W[(size_t)(nBase + (e >> 5)) * ldw + k0 + (e & 31)]));
        }
        __syncthreads();
#pragma unroll
        for (int k8 = 0; k8 < 4; k8++) {
            int kk = k8 * 8;
            uint32_t afr[2][4], bfr[4][2];
#pragma unroll
            for (int mi = 0; mi < 2; mi++) {
                int m = warpM*32 + mi*16 + group;
                afr[mi][0] = __float_as_uint(As[(m    )*PADK + kk + tid4    ]);
                afr[mi][1] = __float_as_uint(As[(m + 8)*PADK + kk + tid4    ]);
                afr[mi][2] = __float_as_uint(As[(m    )*PADK + kk + tid4 + 4]);
                afr[mi][3] = __float_as_uint(As[(m + 8)*PADK + kk + tid4 + 4]);
            }
#pragma unroll
            for (int ni = 0; ni < 4; ni++) {
                int n = warpN*32 + ni*8 + group;
                bfr[ni][0] = __float_as_uint(Ws[n*PADK + kk + tid4    ]);
                bfr[ni][1] = __float_as_uint(Ws[n*PADK + kk + tid4 + 4]);
            }
#pragma unroll
            for (int mi = 0; mi < 2; mi++)
#pragma unroll
                for (int ni = 0; ni < 4; ni++)
                    mma_tf32(acc[mi][ni], afr[mi], bfr[ni]);
        }
        __syncthreads();
    }

#pragma unroll
    for (int mi = 0; mi < 2; mi++)
#pragma unroll
        for (int ni = 0; ni < 4; ni++) {
            int row = warpM*32 + mi*16 + group;
            int col = nBase + warpN*32 + ni*8 + 2*tid4;
            atomicAdd(&C[(size_t)row*ldc + col],         acc[mi][ni][0]);
            atomicAdd(&C[(size_t)row*ldc + col + 1],     acc[mi][ni][1]);
            atomicAdd(&C[(size_t)(row+8)*ldc + col],     acc[mi][ni][2]);
            atomicAdd(&C[(size_t)(row+8)*ldc + col + 1], acc[mi][ni][3]);
        }
}

// ---------------------------------------------------------------------------
__global__ void k_softmax(float* __restrict__ out)
{
    int b = blockIdx.x, tid = threadIdx.x;
    __shared__ float red[256];
    float s0 = g_scores[b*S + tid];
    float s1 = g_scores[b*S + 256 + tid];
    red[tid] = fmaxf(s0, s1);
    __syncthreads();
    for (int off = 128; off > 0; off >>= 1) {
        if (tid < off) red[tid] = fmaxf(red[tid], red[tid + off]);
        __syncthreads();
    }
    float m = red[0];
    __syncthreads();
    float e0 = expf(s0 - m), e1 = expf(s1 - m);
    red[tid] = e0 + e1;
    __syncthreads();
    for (int off = 128; off > 0; off >>= 1) {
        if (tid < off) red[tid] += red[tid + off];
        __syncthreads();
    }
    float inv = 1.f / red[0];
    out[OFF_A + b*S + tid]       = e0 * inv;
    out[OFF_A + b*S + 256 + tid] = e1 * inv;
}

// ---------------------------------------------------------------------------
// context from fp16 enc mirror (halved DRAM traffic)
__global__ void k_context(const __half* __restrict__ ench, const float* __restrict__ out)
{
    int b = blockIdx.x;
    int h = blockIdx.y * 256 + threadIdx.x;
    __shared__ float w[S];
    for (int s = threadIdx.x; s < S; s += 256) w[s] = out[OFF_A + b*S + s];
    __syncthreads();
    const __half* p = ench + (size_t)b * S * H + h;
    float a0 = 0.f, a1 = 0.f, a2 = 0.f, a3 = 0.f;
#pragma unroll 4
    for (int s = 0; s < S; s += 4) {
        a0 += w[s]     * __half2float(p[(size_t)s * H]);
        a1 += w[s + 1] * __half2float(p[(size_t)(s + 1) * H]);
        a2 += w[s + 2] * __half2float(p[(size_t)(s + 2) * H]);
        a3 += w[s + 3] * __half2float(p[(size_t)(s + 3) * H]);
    }
    g_context[b*H + h] = (a0 + a1) + (a2 + a3);
}

// ---------------------------------------------------------------------------
__global__ void k_sim(const float* __restrict__ events,
                      const float* __restrict__ W_gate,
                      float* __restrict__ out)
{
    int b = blockIdx.x;
    int tid = threadIdx.x, warp = tid >> 5, lane = tid & 31;
    __shared__ float t[E];
    if (warp < E) {
        float acc = 0.f;
        for (int h = lane; h < H; h += 32)
            acc += g_context[b*H + h] * events[warp*H + h];
#pragma unroll
        for (int off = 16; off > 0; off >>= 1)
            acc += __shfl_down_sync(0xffffffffu, acc, off);
        if (lane == 0) t[warp] = acc;
    }
    __syncthreads();
    if (tid < E) {
        float s = 0.f;
#pragma unroll
        for (int e = 0; e < E; e++) s += t[e] * W_gate[tid*E + e];
        g_sim[b*E + tid] = s;
        out[OFF_S + b*E + tid] = s;
    }
}

// ---------------------------------------------------------------------------
__global__ void k_gates_init(const float* __restrict__ x,
                             const float* __restrict__ W_ih,
                             const float* __restrict__ b_ih,
                             const float* __restrict__ b_hh)
{
    int b = blockIdx.x;
    int j = blockIdx.y * 256 + threadIdx.x;
    const float* wr = W_ih + (size_t)j * LSTM_IN;
    float v = b_ih[j] + b_hh[j] + x[b] * wr[1034];
#pragma unroll
    for (int e = 0; e < E; e++) v += g_sim[b*E + e] * wr[1024 + e];
    g_gates[b*G4 + j] = v;
}

// ---------------------------------------------------------------------------
__global__ void k_lstm_final(const float* __restrict__ c0,
                             const float* __restrict__ ln_g,
                             const float* __restrict__ ln_b,
                             const float* __restrict__ W_fin,
                             const float* __restrict__ b_fin,
                             float* __restrict__ out)
{
    int b = blockIdx.x, tid = threadIdx.x;
    __shared__ float red[256];
    float hv[4];
    float sum = 0.f;
#pragma unroll
    for (int r = 0; r < 4; r++) {
        int h = r*256 + tid;
        float ig = g_gates[b*G4 + h];
        float fg = g_gates[b*G4 + 1024 + h];
        float gg = g_gates[b*G4 + 2048 + h];
        float og = g_gates[b*G4 + 3072 + h];
        float cn = sigmoidf_(fg) * c0[b*H + h] + sigmoidf_(ig) * tanhf(gg);
        float hn = sigmoidf_(og) * tanhf(cn);
        out[OFF_H + b*H + h] = hn;
        out[OFF_C + b*H + h] = cn;
        hv[r] = hn;
        sum += hn;
    }
    red[tid] = sum; __syncthreads();
    for (int off = 128; off > 0; off >>= 1) {
        if (tid < off) red[tid] += red[tid + off];
        __syncthreads();
    }
    float mu = red[0] * (1.f / H);
    __syncthreads();
    float sq = 0.f;
#pragma unroll
    for (int r = 0; r < 4; r++) { float d = hv[r] - mu; sq += d * d; }
    red[tid] = sq; __syncthreads();
    for (int off = 128; off > 0; off >>= 1) {
        if (tid < off) red[tid] += red[tid + off];
        __syncthreads();
    }
    float rstd = rsqrtf(red[0] * (1.f / H) + 1e-5f);
    __syncthreads();
    float fp = 0.f;
#pragma unroll
    for (int r = 0; r < 4; r++) {
        int h = r*256 + tid;
        float y = (hv[r] - mu) * rstd * ln_g[h] + ln_b[h];
        fp += y * W_fin[h];
    }
    red[tid] = fp; __syncthreads();
    for (int off = 128; off > 0; off >>= 1) {
        if (tid < off) red[tid] += red[tid + off];
        __syncthreads();
    }
    if (tid == 0) out[OFF_FIN + b] = red[0] + b_fin[0];
}

// ---------------------------------------------------------------------------
extern "C" void kernel_launch(void* const* d_in, const int* in_sizes, int n_in,
                              void* d_out, int out_size)
{
    const float* x      = (const float*)d_in[0];
    const float* h0     = (const float*)d_in[1];
    const float* c0     = (const float*)d_in[2];
    const float* enc    = (const float*)d_in[3];
    const float* W_enc  = (const float*)d_in[4];
    const float* W_dec  = (const float*)d_in[5];
    const float* w_val  = (const float*)d_in[6];
    const float* W_gate = (const float*)d_in[7];
    const float* events = (const float*)d_in[8];
    const float* W_ih   = (const float*)d_in[9];
    const float* W_hh   = (const float*)d_in[10];
    const float* b_ih   = (const float*)d_in[11];
    const float* b_hh   = (const float*)d_in[12];
    const float* ln_g   = (const float*)d_in[13];
    const float* ln_b   = (const float*)d_in[14];
    const float* W_fin  = (const float*)d_in[15];
    const float* b_fin  = (const float*)d_in[16];
    float* out = (float*)d_out;

    void* p;
    cudaGetSymbolAddress(&p, g_dec_proj); float*  dec_proj = (float*)p;
    cudaGetSymbolAddress(&p, g_context);  float*  context  = (float*)p;
    cudaGetSymbolAddress(&p, g_gates);    float*  gates    = (float*)p;
    cudaGetSymbolAddress(&p, g_enc_h);    __half* ench     = (__half*)p;
    cudaGetSymbolAddress(&p, g_wenc_h);   __half* wench    = (__half*)p;

    cudaFuncSetAttribute(k_attn_f16, cudaFuncAttributeMaxDynamicSharedMemorySize, ATTN_SMEM);

    k_zero<<<256, 256>>>();

    // fp16 mirrors of enc and W_enc
    k_cvt<<<(B*S*H/4 + 255)/256, 256>>>(enc, ench, B*S*H/4);
    k_cvt<<<(H*H/4 + 255)/256, 256>>>(W_enc, wench, H*H/4);

    // dec_proj = h0 @ W_dec^T (tf32, split-K over 4 chunks, 32 CTAs)
    k_tc64<<<dim3(H / 128, 4), 256>>>(h0, W_dec, H, nullptr, nullptr, 0, dec_proj, H);

    // fused scores via fp16 mma.sync m16n8k16
    k_attn_f16<<<dim3(H / BN, B * S / BM), 256, ATTN_SMEM>>>(ench, wench, w_val);

    k_softmax<<<B, 256>>>(out);
    k_context<<<dim3(B, H / 256), 256>>>(ench, out);
    k_sim<<<B, 320>>>(events, W_gate, out);

    k_gates_init<<<dim3(B, 16), 256>>>(x, W_ih, b_ih, b_hh);
    // gates += context @ W_ih[:, :1024]^T + h0 @ W_hh^T (split-K, 256 CTAs)
    k_tc64<<<dim3(G4 / 128, 8), 256>>>(context, W_ih, LSTM_IN, h0, W_hh, H, gates, G4);

    k_lstm_final<<<B, 256>>>(c0, ln_g, ln_b, W_fin, b_fin, out);
}